// round 16
// baseline (speedup 1.0000x reference)
#include <cuda_runtime.h>
#include <cuda_fp16.h>
#include <math.h>
#include <stdint.h>

#define SEQ   2048
#define HID   2048
#define HQ    16
#define HKV   4
#define DH    128
#define QBN   32
#define BSZ   64
#define GHD   128
#define INTER 5632
#define NQKV  3072
#define NGU   11264

#define SCALE_INV_SQRT_128 0.08838834764831845f

// ================= helpers =================
__device__ __forceinline__ uint32_t smem_u32(const void* p) {
    uint32_t a;
    asm("{ .reg .u64 t; cvta.to.shared.u64 t, %1; cvt.u32.u64 %0, t; }" : "=r"(a) : "l"(p));
    return a;
}
__device__ __forceinline__ void cp_async16(uint32_t saddr, const void* gptr) {
    asm volatile("cp.async.cg.shared.global [%0], [%1], 16;" :: "r"(saddr), "l"(gptr));
}
__device__ __forceinline__ void cp_commit() { asm volatile("cp.async.commit_group;"); }

#define LDSM_X4(r0, r1, r2, r3, addr) \
    asm volatile("ldmatrix.sync.aligned.m8n8.x4.shared.b16 {%0,%1,%2,%3}, [%4];" \
        : "=r"(r0), "=r"(r1), "=r"(r2), "=r"(r3) : "r"(addr))

#define MMAF16(c, a, b0r, b1r) \
    asm volatile("mma.sync.aligned.m16n8k16.row.col.f32.f16.f16.f32 " \
        "{%0,%1,%2,%3}, {%4,%5,%6,%7}, {%8,%9}, {%0,%1,%2,%3};" \
        : "+f"((c)[0]), "+f"((c)[1]), "+f"((c)[2]), "+f"((c)[3]) \
        : "r"((a)[0]), "r"((a)[1]), "r"((a)[2]), "r"((a)[3]), "r"(b0r), "r"(b1r))

static __device__ __forceinline__ uint32_t sw128(uint32_t o) { return o ^ ((o >> 3) & 0x70); }

__device__ __forceinline__ float siluf(float x) { return x / (1.f + __expf(-x)); }

// ================= device scratch =================
__device__ float g_qkv [SEQ*NQKV];
__device__ float g_qp  [QBN*HQ*DH];
__device__ float g_kp  [QBN*HKV*DH];
__device__ float g_qg  [QBN*HQ*GHD];
__device__ float g_kg  [QBN*HKV*GHD];
__device__ unsigned char g_keep[HQ*QBN*QBN];
__device__ float g_h2  [SEQ*HID];

__device__ __half g_Wqkv2[NQKV*HID];
__device__ __half g_Wo2  [2048*2048];
__device__ __half g_Wgu2 [NGU*HID];      // interleaved: row 2j = gate_j, 2j+1 = up_j
__device__ __half g_Wd2  [2048*INTER];
__device__ __half g_ha2  [SEQ*HID];
__device__ __half g_oa2  [SEQ*HID];
__device__ __half g_h3a2 [SEQ*HID];
__device__ __half g_gt2  [SEQ*INTER];
__device__ __half g_qf16 [SEQ*HQ*DH];
__device__ __half g_kf16 [SEQ*HKV*DH];
__device__ __half g_vt16 [HKV*DH*SEQ];

// ===== stream resources (created pre-main in static init) =====
struct AuxRes {
    cudaStream_t s2, s3;
    cudaEvent_t root, evQKV, evQKVm, evWo, evGU, evWd, evGate, evVt;
    AuxRes() {
        cudaStreamCreateWithFlags(&s2, cudaStreamNonBlocking);
        cudaStreamCreateWithFlags(&s3, cudaStreamNonBlocking);
        cudaEventCreateWithFlags(&root,   cudaEventDisableTiming);
        cudaEventCreateWithFlags(&evQKV,  cudaEventDisableTiming);
        cudaEventCreateWithFlags(&evQKVm, cudaEventDisableTiming);
        cudaEventCreateWithFlags(&evWo,   cudaEventDisableTiming);
        cudaEventCreateWithFlags(&evGU,   cudaEventDisableTiming);
        cudaEventCreateWithFlags(&evWd,   cudaEventDisableTiming);
        cudaEventCreateWithFlags(&evGate, cudaEventDisableTiming);
        cudaEventCreateWithFlags(&evVt,   cudaEventDisableTiming);
    }
};
static AuxRes g_aux;

// ===== fused QKV weight conversion: fp32 [K,N]x3 -> fp16 [3072, K] =====
__global__ void wconv3_kernel(const float* __restrict__ Wq, const float* __restrict__ Wk,
                              const float* __restrict__ Wv, __half* __restrict__ y) {
    __shared__ float tile[32][33];
    int n0 = blockIdx.x * 32, k0 = blockIdx.y * 32;
    const float* W; int sN, c0;
    if (n0 < 2048)      { W = Wq; sN = 2048; c0 = n0; }
    else if (n0 < 2560) { W = Wk; sN = 512;  c0 = n0 - 2048; }
    else                { W = Wv; sN = 512;  c0 = n0 - 2560; }
    for (int i = threadIdx.y; i < 32; i += 8)
        tile[i][threadIdx.x] = W[(size_t)(k0 + i) * sN + c0 + threadIdx.x];
    __syncthreads();
    for (int i = threadIdx.y; i < 32; i += 8) {
        int n = n0 + i, k = k0 + threadIdx.x;
        y[(size_t)n * HID + k] = __float2half_rn(tile[threadIdx.x][i]);
    }
}

// ===== weight conversion: fp32 [K,N] -> fp16 [N,K] =====
__global__ void wconv_kernel(const float* __restrict__ W, __half* __restrict__ y,
                             int K, int N) {
    __shared__ float tile[32][33];
    int n0 = blockIdx.x * 32, k0 = blockIdx.y * 32;
    for (int i = threadIdx.y; i < 32; i += 8)
        tile[i][threadIdx.x] = W[(size_t)(k0 + i) * N + n0 + threadIdx.x];
    __syncthreads();
    for (int i = threadIdx.y; i < 32; i += 8) {
        int n = n0 + i, k = k0 + threadIdx.x;
        y[(size_t)n * K + k] = __float2half_rn(tile[threadIdx.x][i]);
    }
}

// ===== interleaved gate/up weight conversion: rows 2j=gate_j, 2j+1=up_j =====
__global__ void wconvGU_kernel(const float* __restrict__ Wg, const float* __restrict__ Wu,
                               __half* __restrict__ y) {
    __shared__ float tg[32][33];
    __shared__ float tu[32][33];
    int j0 = blockIdx.x * 32, k0 = blockIdx.y * 32;
    for (int i = threadIdx.y; i < 32; i += 8) {
        tg[i][threadIdx.x] = Wg[(size_t)(k0 + i) * INTER + j0 + threadIdx.x];
        tu[i][threadIdx.x] = Wu[(size_t)(k0 + i) * INTER + j0 + threadIdx.x];
    }
    __syncthreads();
    for (int i = threadIdx.y; i < 32; i += 8) {
        int j = j0 + i, k = k0 + threadIdx.x;
        y[(size_t)(2 * j)     * HID + k] = __float2half_rn(tg[threadIdx.x][i]);
        y[(size_t)(2 * j + 1) * HID + k] = __float2half_rn(tu[threadIdx.x][i]);
    }
}

// ===== RMSNorm fused with fp16 conversion (vectorized) =====
__global__ void rmsconv_kernel(const float* __restrict__ x, const float* __restrict__ w,
                               __half* __restrict__ y) {
    const int row = blockIdx.x;
    const float4* xr4 = (const float4*)(x + (size_t)row * HID);
    const float4* w4  = (const float4*)w;
    const int t = threadIdx.x;

    float4 v0 = xr4[t], v1 = xr4[t + 256];
    float s = v0.x*v0.x + v0.y*v0.y + v0.z*v0.z + v0.w*v0.w
            + v1.x*v1.x + v1.y*v1.y + v1.z*v1.z + v1.w*v1.w;
    __shared__ float red[256];
    red[t] = s; __syncthreads();
    for (int st = 128; st > 0; st >>= 1) {
        if (t < st) red[t] += red[t + st];
        __syncthreads();
    }
    const float r = rsqrtf(red[0] / (float)HID + 1e-6f);

    float4 wa = w4[t], wb = w4[t + 256];
    __half2* yo = (__half2*)(y + (size_t)row * HID);
    yo[t * 2]           = __floats2half2_rn(wa.x * v0.x * r, wa.y * v0.y * r);
    yo[t * 2 + 1]       = __floats2half2_rn(wa.z * v0.z * r, wa.w * v0.w * r);
    yo[(t + 256) * 2]   = __floats2half2_rn(wb.x * v1.x * r, wb.y * v1.y * r);
    yo[(t + 256) * 2 + 1] = __floats2half2_rn(wb.z * v1.z * r, wb.w * v1.w * r);
}

// ====== fp16 HMMA GEMM, segs-limb A; optional fused SiLU(g)*u fp16 output ======
#define HG_SMEM 65536

__global__ void __launch_bounds__(256, 2) hgemm_kernel(
    const __half* __restrict__ A, const __half* __restrict__ B,
    const float* __restrict__ b1, const float* __restrict__ b2, const float* __restrict__ b3,
    int n1, int n2,
    const float* __restrict__ res,
    float* __restrict__ C, __half* __restrict__ Chalf,
    int N, int K, int segs)
{
    extern __shared__ char smraw[];
    const uint32_t smu = smem_u32(smraw);
    const int tid = threadIdx.x;
    const int lane = tid & 31, wid = tid >> 5;
    const int wm = wid >> 2, wn = wid & 3;
    const size_t ldaA = (size_t)segs * K;
    const size_t ldaB = (size_t)K;
    const int kpseg = K >> 6;
    const int nch = segs * kpseg;
    const size_t arow0 = (size_t)blockIdx.x * 128;
    const size_t brow0 = (size_t)blockIdx.y * 128;

    const uint32_t xm = (uint32_t)((lane & 7) << 4);
    uint32_t kbx[4];
#pragma unroll
    for (int ks = 0; ks < 4; ks++)
        kbx[ks] = ((uint32_t)(ks * 32 + ((lane >> 4) << 4))) ^ xm;
    uint32_t rowA[4], rowB[2];
#pragma unroll
    for (int mt = 0; mt < 4; mt++)
        rowA[mt] = (uint32_t)((wm << 6) + (lane & 15) + (mt << 4)) * 128u;
#pragma unroll
    for (int nt2 = 0; nt2 < 2; nt2++)
        rowB[nt2] = (uint32_t)((wn << 5) + (lane & 15) + (nt2 << 4)) * 128u;

    float acc[4][4][4];
#pragma unroll
    for (int i = 0; i < 4; i++)
#pragma unroll
        for (int j = 0; j < 4; j++)
#pragma unroll
            for (int t = 0; t < 4; t++) acc[i][j][t] = 0.f;

    auto issue = [&](int ch, int b) {
        int seg = ch / kpseg;
        int kk = (ch - seg * kpseg) << 6;
        const __half* Ab = A + (size_t)seg * K + kk;
        const __half* Bb = B + kk;
        uint32_t abase = smu + b * 32768;
        uint32_t bbase = abase + 16384;
#pragma unroll
        for (int i = 0; i < 4; i++) {
            int u = i * 256 + tid;
            int r = u >> 3, c = u & 7;
            uint32_t so = sw128((uint32_t)(r * 128 + c * 16));
            cp_async16(abase + so, Ab + (arow0 + r) * ldaA + c * 8);
            cp_async16(bbase + so, Bb + (brow0 + r) * ldaB + c * 8);
        }
        cp_commit();
    };

    issue(0, 0);

    for (int ch = 0; ch < nch; ch++) {
        const int b = ch & 1;
        if (ch + 1 < nch) {
            issue(ch + 1, b ^ 1);
            asm volatile("cp.async.wait_group 1;");
        } else {
            asm volatile("cp.async.wait_group 0;");
        }
        __syncthreads();

        const uint32_t abuf = smu + b * 32768;
        const uint32_t bbuf = abuf + 16384;

#pragma unroll
        for (int ks = 0; ks < 4; ks++) {
            uint32_t a[4][4];
#pragma unroll
            for (int mt = 0; mt < 4; mt++)
                LDSM_X4(a[mt][0], a[mt][1], a[mt][2], a[mt][3],
                        abuf + rowA[mt] + kbx[ks]);
            uint32_t bf[4][2];
#pragma unroll
            for (int nt2 = 0; nt2 < 2; nt2++) {
                uint32_t t0, t1, t2, t3;
                LDSM_X4(t0, t1, t2, t3, bbuf + rowB[nt2] + kbx[ks]);
                bf[nt2 * 2 + 0][0] = t0; bf[nt2 * 2 + 0][1] = t2;
                bf[nt2 * 2 + 1][0] = t1; bf[nt2 * 2 + 1][1] = t3;
            }
#pragma unroll
            for (int mt = 0; mt < 4; mt++)
#pragma unroll
                for (int nt = 0; nt < 4; nt++)
                    MMAF16(acc[mt][nt], a[mt], bf[nt][0], bf[nt][1]);
        }
        __syncthreads();
    }

    const int rbase = (int)arow0 + (wm << 6) + (lane >> 2);
    const int cbase = (int)brow0 + (wn << 5) + ((lane & 3) << 1);

    if (Chalf) {
        const int No = N >> 1;
#pragma unroll
        for (int nt = 0; nt < 4; nt++) {
            const int col = cbase + (nt << 3);
            const int oc = col >> 1;
#pragma unroll
            for (int mt = 0; mt < 4; mt++) {
                const int row = rbase + (mt << 4);
                float v0 = siluf(acc[mt][nt][0]) * acc[mt][nt][1];
                Chalf[(size_t)row * No + oc] = __float2half_rn(v0);
                float v1 = siluf(acc[mt][nt][2]) * acc[mt][nt][3];
                Chalf[(size_t)(row + 8) * No + oc] = __float2half_rn(v1);
            }
        }
        return;
    }

#pragma unroll
    for (int nt = 0; nt < 4; nt++) {
        const int col = cbase + (nt << 3);
        float bv0 = 0.f, bv1 = 0.f;
        if (b1) {
            if (col < n1)       { bv0 = b1[col];      bv1 = b1[col + 1]; }
            else if (col < n2)  { bv0 = b2[col - n1]; bv1 = b2[col - n1 + 1]; }
            else                { bv0 = b3[col - n2]; bv1 = b3[col - n2 + 1]; }
        }
#pragma unroll
        for (int mt = 0; mt < 4; mt++) {
            const int row = rbase + (mt << 4);
            size_t gi = (size_t)row * N + col;
            float v0 = acc[mt][nt][0] + bv0, v1 = acc[mt][nt][1] + bv1;
            if (res) { v0 += res[gi]; v1 += res[gi + 1]; }
            *(float2*)(C + gi) = make_float2(v0, v1);
            size_t gi2 = gi + (size_t)8 * N;
            float v2 = acc[mt][nt][2] + bv0, v3 = acc[mt][nt][3] + bv1;
            if (res) { v2 += res[gi2]; v3 += res[gi2 + 1]; }
            *(float2*)(C + gi2) = make_float2(v2, v3);
        }
    }
}

// ================= small fp32 SGEMM (gate path only) =================
__global__ void __launch_bounds__(256) sgemm_kernel(
    const float* __restrict__ A, const float* __restrict__ B,
    float* __restrict__ C, int M, int N, int K)
{
    __shared__ float As[8][128];
    __shared__ float Bs[8][128];
    const int tid = threadIdx.x;
    const int bx = blockIdx.x * 128;
    const int by = blockIdx.y * 128;
    const int tx = tid & 15;
    const int ty = tid >> 4;
    const int arow = tid >> 1;
    const int acol = (tid & 1) << 2;
    const int brow = tid >> 5;
    const int bcol = (tid & 31) << 2;

    const float* Ap = A + (size_t)(by + arow) * K + acol;
    const float* Bp = B + (size_t)brow * N + bx + bcol;

    float acc[8][8];
#pragma unroll
    for (int i = 0; i < 8; i++)
#pragma unroll
        for (int j = 0; j < 8; j++) acc[i][j] = 0.f;

    for (int k0 = 0; k0 < K; k0 += 8) {
        float4 av = *(const float4*)Ap;
        As[acol + 0][arow] = av.x;
        As[acol + 1][arow] = av.y;
        As[acol + 2][arow] = av.z;
        As[acol + 3][arow] = av.w;
        *(float4*)&Bs[brow][bcol] = *(const float4*)Bp;
        __syncthreads();
#pragma unroll
        for (int kk = 0; kk < 8; kk++) {
            float a[8], bb[8];
            *(float4*)&a[0] = *(const float4*)&As[kk][ty * 8];
            *(float4*)&a[4] = *(const float4*)&As[kk][ty * 8 + 4];
            *(float4*)&bb[0] = *(const float4*)&Bs[kk][tx * 8];
            *(float4*)&bb[4] = *(const float4*)&Bs[kk][tx * 8 + 4];
#pragma unroll
            for (int i = 0; i < 8; i++)
#pragma unroll
                for (int j = 0; j < 8; j++)
                    acc[i][j] += a[i] * bb[j];
        }
        __syncthreads();
        Ap += 8;
        Bp += (size_t)8 * N;
    }

    const int row0 = by + ty * 8;
    const int col0 = bx + tx * 8;
#pragma unroll
    for (int i = 0; i < 8; i++)
#pragma unroll
        for (int j = 0; j < 8; j++)
            C[(size_t)(row0 + i) * N + col0 + j] = acc[i][j];
}

// ================= pooling / gate =================
__global__ void pool_kernel(const float* __restrict__ x, int stride,
                            float* __restrict__ out, int H) {
    int qb = blockIdx.x, h = blockIdx.y, d = threadIdx.x;
    float s = 0.f;
    for (int i = 0; i < BSZ; i++)
        s += x[(size_t)(qb * BSZ + i) * stride + h * DH + d];
    out[((size_t)qb * H + h) * DH + d] = s * (1.f / (float)BSZ);
}

__global__ void gate_kernel(const float* __restrict__ qg, const float* __restrict__ kg,
                            unsigned char* __restrict__ keep) {
    int h = blockIdx.x, qb = blockIdx.y, kb = threadIdx.x;
    const float* qv = qg + ((size_t)qb * HQ + h) * GHD;
    const float* kv = kg + ((size_t)kb * HKV + (h >> 2)) * GHD;
    float s = 0.f;
    for (int d = 0; d < GHD; d++) s += qv[d] * kv[d];
    s *= SCALE_INV_SQRT_128;
    if (kb > qb) s = -1e30f;
    float m = s;
    for (int off = 16; off > 0; off >>= 1)
        m = fmaxf(m, __shfl_xor_sync(0xffffffffu, m, off));
    float e = expf(s - m);
    float sum = e;
    for (int off = 16; off > 0; off >>= 1)
        sum += __shfl_xor_sync(0xffffffffu, sum, off);
    float gate = e / sum;
    bool kp = (kb <= qb) && ((gate >= 0.004f) || (kb == qb));
    keep[((size_t)h * QBN + qb) * QBN + kb] = kp ? 1 : 0;
}

// ===== RoPE + fp16 conversion =====
__global__ void ropeconv_kernel(const float* __restrict__ qkv,
                                const float* __restrict__ cs, const float* __restrict__ sn,
                                __half* __restrict__ qf, __half* __restrict__ kf) {
    int t = blockIdx.x;
    const float* row = qkv + (size_t)t * NQKV;
    const float* c = cs + (size_t)t * DH;
    const float* s = sn + (size_t)t * DH;
    for (int i = threadIdx.x; i < HQ * 64; i += 256) {
        int hh = i >> 6, d = i & 63;
        float x1 = row[hh * DH + d], x2 = row[hh * DH + d + 64];
        qf[(size_t)t * (HQ*DH) + hh * DH + d] =
            __float2half_rn((x1 * c[d] - x2 * s[d]) * SCALE_INV_SQRT_128);
        qf[(size_t)t * (HQ*DH) + hh * DH + d + 64] =
            __float2half_rn((x2 * c[d + 64] + x1 * s[d + 64]) * SCALE_INV_SQRT_128);
    }
    for (int i = threadIdx.x; i < HKV * 64; i += 256) {
        int hh = i >> 6, d = i & 63;
        float x1 = row[2048 + hh * DH + d], x2 = row[2048 + hh * DH + d + 64];
        kf[(size_t)t * (HKV*DH) + hh * DH + d] =
            __float2half_rn(x1 * c[d] - x2 * s[d]);
        kf[(size_t)t * (HKV*DH) + hh * DH + d + 64] =
            __float2half_rn(x2 * c[d + 64] + x1 * s[d + 64]);
    }
}

// ===== V transpose + fp16 =====
__global__ void vconvt_kernel(const float* __restrict__ qkv, __half* __restrict__ vt) {
    __shared__ float tile[32][33];
    int t0 = blockIdx.x * 32, d0 = blockIdx.y * 32, hk = blockIdx.z;
    for (int i = threadIdx.y; i < 32; i += 8)
        tile[i][threadIdx.x] = qkv[(size_t)(t0 + i) * NQKV + 2560 + hk * DH + d0 + threadIdx.x];
    __syncthreads();
    for (int i = threadIdx.y; i < 32; i += 8) {
        int d = d0 + i, t = t0 + threadIdx.x;
        vt[((size_t)hk * DH + d) * SEQ + t] = __float2half_rn(tile[threadIdx.x][i]);
    }
}

// ================= fp16 tensor-core block-sparse flash attention =================
#define QKP 136
#define VTP 72
#define PSP 72
#define FS_OFF 62464
#define ATTN_SMEM (FS_OFF + 448*4)

__global__ void __launch_bounds__(256, 2) attn_kernel(
    const __half* __restrict__ qf, const __half* __restrict__ kf,
    const __half* __restrict__ vt,
    const unsigned char* __restrict__ keep, __half* __restrict__ oa2)
{
    extern __shared__ char smc[];
    __half* QS = (__half*)smc;
    __half* KS = QS + 64 * QKP;
    __half* VT = KS + 64 * QKP;
    __half* PS = VT + 128 * VTP;
    float* fs = (float*)(smc + FS_OFF);
    float* ARM = fs; float* ARL = fs + 128;
    float* ROWM = fs + 256; float* ROWL = fs + 320; float* ALF = fs + 384;

    const int qb = QBN - 1 - blockIdx.x;
    const int h = blockIdx.y;
    const int hk = h >> 2;
    const int tid = threadIdx.x;
    const int lane = tid & 31, wid = tid >> 5;
    const int rw = wid & 3, cw = wid >> 2;
    const int g = lane >> 2, qd = lane & 3;
    const int r0 = rw * 16 + g;
    const int r1 = r0 + 8;
    const int q2 = qd * 2;

    for (int i = tid; i < 64 * 16; i += 256) {
        int r = i >> 4, c = i & 15;
        *(uint4*)&QS[r * QKP + c * 8] =
            *(const uint4*)&qf[(size_t)(qb * 64 + r) * (HQ*DH) + h * DH + c * 8];
    }
    if (tid < 64) { ROWM[tid] = -1e30f; ROWL[tid] = 0.f; }

    float oacc[8][4];
#pragma unroll
    for (int i = 0; i < 8; i++)
#pragma unroll
        for (int j = 0; j < 4; j++) oacc[i][j] = 0.f;

    const unsigned char* krow = keep + ((size_t)h * QBN + qb) * QBN;

    for (int kb = 0; kb <= qb; kb++) {
        if (!krow[kb]) continue;
        __syncthreads();

        for (int i = tid; i < 64 * 16; i += 256) {
            int r = i >> 4, c = i & 15;
            *(uint4*)&KS[r * QKP + c * 8] =
                *(const uint4*)&kf[(size_t)(kb * 64 + r) * (HKV*DH) + hk * DH + c * 8];
        }
        for (int i = tid; i < 128 * 8; i += 256) {
            int d = i >> 3, c = i & 7;
            *(uint4*)&VT[d * VTP + c * 8] =
                *(const uint4*)&vt[((size_t)hk * DH + d) * SEQ + kb * 64 + c * 8];
        }
        __syncthreads();

        float sacc[4][4];
#pragma unroll
        for (int i = 0; i < 4; i++)
#pragma unroll
            for (int j = 0; j < 4; j++) sacc[i][j] = 0.f;

#pragma unroll
        for (int kc = 0; kc < 8; kc++) {
            const int k0 = kc * 16;
            uint32_t a[4];
            a[0] = *(const uint32_t*)&QS[r0 * QKP + k0 + q2];
            a[1] = *(const uint32_t*)&QS[r1 * QKP + k0 + q2];
            a[2] = *(const uint32_t*)&QS[r0 * QKP + k0 + q2 + 8];
            a[3] = *(const uint32_t*)&QS[r1 * QKP + k0 + q2 + 8];
#pragma unroll
            for (int nt = 0; nt < 4; nt++) {
                const int n = cw * 32 + nt * 8 + g;
                uint32_t b0 = *(const uint32_t*)&KS[n * QKP + k0 + q2];
                uint32_t b1 = *(const uint32_t*)&KS[n * QKP + k0 + q2 + 8];
                MMAF16(sacc[nt], a, b0, b1);
            }
        }

        if (kb == qb) {
#pragma unroll
            for (int nt = 0; nt < 4; nt++) {
                const int c0 = cw * 32 + nt * 8 + q2;
                if (c0 > r0)     sacc[nt][0] = -1e30f;
                if (c0 + 1 > r0) sacc[nt][1] = -1e30f;
                if (c0 > r1)     sacc[nt][2] = -1e30f;
                if (c0 + 1 > r1) sacc[nt][3] = -1e30f;
            }
        }

        float m0 = -1e30f, m1 = -1e30f;
#pragma unroll
        for (int nt = 0; nt < 4; nt++) {
            m0 = fmaxf(m0, fmaxf(sacc[nt][0], sacc[nt][1]));
            m1 = fmaxf(m1, fmaxf(sacc[nt][2], sacc[nt][3]));
        }
        m0 = fmaxf(m0, __shfl_xor_sync(0xffffffffu, m0, 1));
        m0 = fmaxf(m0, __shfl_xor_sync(0xffffffffu, m0, 2));
        m1 = fmaxf(m1, __shfl_xor_sync(0xffffffffu, m1, 1));
        m1 = fmaxf(m1, __shfl_xor_sync(0xffffffffu, m1, 2));
        if (qd == 0) {
            ARM[cw * 64 + r0] = m0;
            ARM[cw * 64 + r1] = m1;
        }
        __syncthreads();

        if (tid < 64) {
            float newm = fmaxf(ROWM[tid], fmaxf(ARM[tid], ARM[64 + tid]));
            ALF[tid] = __expf(ROWM[tid] - newm);
            ROWM[tid] = newm;
        }
        __syncthreads();

        const float nm0 = ROWM[r0];
        const float nm1 = ROWM[r1];
        float l0 = 0.f, l1 = 0.f;
#pragma unroll
        for (int nt = 0; nt < 4; nt++) {
            const int c0 = cw * 32 + nt * 8 + q2;
            float p0 = __expf(sacc[nt][0] - nm0);
            float p1 = __expf(sacc[nt][1] - nm0);
            float p2 = __expf(sacc[nt][2] - nm1);
            float p3 = __expf(sacc[nt][3] - nm1);
            l0 += p0 + p1; l1 += p2 + p3;
            *(__half2*)&PS[r0 * PSP + c0] = __floats2half2_rn(p0, p1);
            *(__half2*)&PS[r1 * PSP + c0] = __floats2half2_rn(p2, p3);
        }
        l0 += __shfl_xor_sync(0xffffffffu, l0, 1);
        l0 += __shfl_xor_sync(0xffffffffu, l0, 2);
        l1 += __shfl_xor_sync(0xffffffffu, l1, 1);
        l1 += __shfl_xor_sync(0xffffffffu, l1, 2);
        if (qd == 0) {
            ARL[cw * 64 + r0] = l0;
            ARL[cw * 64 + r1] = l1;
        }
        const float al0 = ALF[r0];
        const float al1 = ALF[r1];
#pragma unroll
        for (int nt = 0; nt < 8; nt++) {
            oacc[nt][0] *= al0; oacc[nt][1] *= al0;
            oacc[nt][2] *= al1; oacc[nt][3] *= al1;
        }
        __syncthreads();

        if (tid < 64)
            ROWL[tid] = ROWL[tid] * ALF[tid] + ARL[tid] + ARL[64 + tid];

#pragma unroll
        for (int kc = 0; kc < 4; kc++) {
            const int k0 = kc * 16;
            uint32_t a[4];
            a[0] = *(const uint32_t*)&PS[r0 * PSP + k0 + q2];
            a[1] = *(const uint32_t*)&PS[r1 * PSP + k0 + q2];
            a[2] = *(const uint32_t*)&PS[r0 * PSP + k0 + q2 + 8];
            a[3] = *(const uint32_t*)&PS[r1 * PSP + k0 + q2 + 8];
#pragma unroll
            for (int nt = 0; nt < 8; nt++) {
                const int n = cw * 64 + nt * 8 + g;
                uint32_t b0 = *(const uint32_t*)&VT[n * VTP + k0 + q2];
                uint32_t b1 = *(const uint32_t*)&VT[n * VTP + k0 + q2 + 8];
                MMAF16(oacc[nt], a, b0, b1);
            }
        }
    }

    __syncthreads();
    const float inv0 = 1.f / ROWL[r0];
    const float inv1 = 1.f / ROWL[r1];
    const size_t grow0 = (size_t)(qb * 64 + r0);
    const size_t grow1 = (size_t)(qb * 64 + r1);
#pragma unroll
    for (int nt = 0; nt < 8; nt++) {
        const int col = h * DH + cw * 64 + nt * 8 + q2;
        *(__half2*)(oa2 + grow0 * HID + col) =
            __floats2half2_rn(oacc[nt][0] * inv0, oacc[nt][1] * inv0);
        *(__half2*)(oa2 + grow1 * HID + col) =
            __floats2half2_rn(oacc[nt][2] * inv1, oacc[nt][3] * inv1);
    }
}

// ================= launch =================
extern "C" void kernel_launch(void* const* d_in, const int* in_sizes, int n_in,
                              void* d_out, int out_size) {
    const float* hidden = (const float*)d_in[0];
    const float* cosp   = (const float*)d_in[1];
    const float* sinp   = (const float*)d_in[2];
    const float* ln1    = (const float*)d_in[3];
    const float* ln2    = (const float*)d_in[4];
    const float* Wq     = (const float*)d_in[5];
    const float* bq     = (const float*)d_in[6];
    const float* Wk     = (const float*)d_in[7];
    const float* bk     = (const float*)d_in[8];
    const float* Wv     = (const float*)d_in[9];
    const float* bv     = (const float*)d_in[10];
    const float* Wo     = (const float*)d_in[11];
    const float* gWq    = (const float*)d_in[12];
    const float* gWk    = (const float*)d_in[13];
    const float* Wgate  = (const float*)d_in[14];
    const float* Wup    = (const float*)d_in[15];
    const float* Wdown  = (const float*)d_in[16];
    float* out = (float*)d_out;

    float *qkv, *qp, *kp, *qg, *kg, *h2;
    unsigned char* keep;
    __half *Wqkv2, *Wo2, *Wgu2, *Wd2, *ha2, *oa2, *h3a2, *gt2, *qf16, *kf16, *vt16;
    cudaGetSymbolAddress((void**)&qkv,  g_qkv);
    cudaGetSymbolAddress((void**)&qp,   g_qp);
    cudaGetSymbolAddress((void**)&kp,   g_kp);
    cudaGetSymbolAddress((void**)&qg,   g_qg);
    cudaGetSymbolAddress((void**)&kg,   g_kg);
    cudaGetSymbolAddress((void**)&keep, g_keep);
    cudaGetSymbolAddress((void**)&h2,   g_h2);
    cudaGetSymbolAddress((void**)&Wqkv2, g_Wqkv2);
    cudaGetSymbolAddress((void**)&Wo2,  g_Wo2);
    cudaGetSymbolAddress((void**)&Wgu2, g_Wgu2);
    cudaGetSymbolAddress((void**)&Wd2,  g_Wd2);
    cudaGetSymbolAddress((void**)&ha2,  g_ha2);
    cudaGetSymbolAddress((void**)&oa2,  g_oa2);
    cudaGetSymbolAddress((void**)&h3a2, g_h3a2);
    cudaGetSymbolAddress((void**)&gt2,  g_gt2);
    cudaGetSymbolAddress((void**)&qf16, g_qf16);
    cudaGetSymbolAddress((void**)&kf16, g_kf16);
    cudaGetSymbolAddress((void**)&vt16, g_vt16);

    cudaFuncSetAttribute(hgemm_kernel, cudaFuncAttributeMaxDynamicSharedMemorySize, HG_SMEM);
    cudaFuncSetAttribute(attn_kernel, cudaFuncAttributeMaxDynamicSharedMemorySize, ATTN_SMEM);

    dim3 w8(32, 8);
    cudaStream_t s2 = g_aux.s2;
    cudaStream_t s3 = g_aux.s3;

    // ---- side stream: QKV weights first, then Wo; gate chain after QKV GEMM ----
    cudaEventRecord(g_aux.root, 0);
    cudaStreamWaitEvent(s2, g_aux.root, 0);
    wconv3_kernel<<<dim3(NQKV/32, HID/32), w8, 0, s2>>>(Wq, Wk, Wv, Wqkv2);
    cudaEventRecord(g_aux.evQKV, s2);
    wconv_kernel<<<dim3(HID/32, HID/32), w8, 0, s2>>>(Wo, Wo2, HID, HID);
    cudaEventRecord(g_aux.evWo, s2);

    // ---- main chain ----
    rmsconv_kernel<<<SEQ, 256>>>(hidden, ln1, ha2);
    cudaStreamWaitEvent(0, g_aux.evQKV, 0);
    hgemm_kernel<<<dim3(SEQ/128, NQKV/128), 256, HG_SMEM>>>(
        ha2, Wqkv2, bq, bk, bv, 2048, 2560, nullptr, qkv, nullptr, NQKV, HID, 1);
    cudaEventRecord(g_aux.evQKVm, 0);

    // gate chain on s2 (after QKV output ready)
    cudaStreamWaitEvent(s2, g_aux.evQKVm, 0);
    pool_kernel<<<dim3(QBN, HQ), DH, 0, s2>>>(qkv, NQKV, qp, HQ);
    pool_kernel<<<dim3(QBN, HKV), DH, 0, s2>>>(qkv + 2048, NQKV, kp, HKV);
    sgemm_kernel<<<dim3(GHD/128, (QBN*HQ)/128), 256, 0, s2>>>(qp, gWq, qg, QBN*HQ, GHD, DH);
    sgemm_kernel<<<dim3(GHD/128, (QBN*HKV)/128), 256, 0, s2>>>(kp, gWk, kg, QBN*HKV, GHD, DH);
    gate_kernel<<<dim3(HQ, QBN), 32, 0, s2>>>(qg, kg, keep);
    cudaEventRecord(g_aux.evGate, s2);
    wconvGU_kernel<<<dim3(INTER/32, HID/32), w8, 0, s2>>>(Wgate, Wup, Wgu2);
    cudaEventRecord(g_aux.evGU, s2);
    wconv_kernel<<<dim3(HID/32, INTER/32), w8, 0, s2>>>(Wdown, Wd2, INTER, HID);
    cudaEventRecord(g_aux.evWd, s2);

    // V transpose on s3, parallel with RoPE on main
    cudaStreamWaitEvent(s3, g_aux.evQKVm, 0);
    vconvt_kernel<<<dim3(SEQ/32, DH/32, HKV), w8, 0, s3>>>(qkv, vt16);
    cudaEventRecord(g_aux.evVt, s3);

    ropeconv_kernel<<<SEQ, 256>>>(qkv, cosp, sinp, qf16, kf16);

    cudaStreamWaitEvent(0, g_aux.evVt, 0);
    cudaStreamWaitEvent(0, g_aux.evGate, 0);
    attn_kernel<<<dim3(QBN, HQ), 256, ATTN_SMEM>>>(qf16, kf16, vt16, keep, oa2);

    cudaStreamWaitEvent(0, g_aux.evWo, 0);
    hgemm_kernel<<<dim3(SEQ/128, HID/128), 256, HG_SMEM>>>(
        oa2, Wo2, nullptr, nullptr, nullptr, HID, HID, hidden, h2, nullptr, HID, HQ*DH, 1);

    rmsconv_kernel<<<SEQ, 256>>>(h2, ln2, h3a2);

    cudaStreamWaitEvent(0, g_aux.evGU, 0);
    hgemm_kernel<<<dim3(SEQ/128, NGU/128), 256, HG_SMEM>>>(
        h3a2, Wgu2, nullptr, nullptr, nullptr, NGU, NGU, nullptr, nullptr, gt2, NGU, HID, 1);

    cudaStreamWaitEvent(0, g_aux.evWd, 0);
    hgemm_kernel<<<dim3(SEQ/128, HID/128), 256, HG_SMEM>>>(
        gt2, Wd2, nullptr, nullptr, nullptr, HID, HID, h2, out, nullptr, HID, INTER, 1);
}

// round 17
// speedup vs baseline: 1.0560x; 1.0560x over previous
#include <cuda_runtime.h>
#include <cuda_fp16.h>
#include <math.h>
#include <stdint.h>

#define SEQ   2048
#define HID   2048
#define HQ    16
#define HKV   4
#define DH    128
#define QBN   32
#define BSZ   64
#define GHD   128
#define INTER 5632
#define NQKV  3072
#define NGU   11264

#define SCALE_INV_SQRT_128 0.08838834764831845f

// ================= helpers =================
__device__ __forceinline__ uint32_t smem_u32(const void* p) {
    uint32_t a;
    asm("{ .reg .u64 t; cvta.to.shared.u64 t, %1; cvt.u32.u64 %0, t; }" : "=r"(a) : "l"(p));
    return a;
}
__device__ __forceinline__ void cp_async16(uint32_t saddr, const void* gptr) {
    asm volatile("cp.async.cg.shared.global [%0], [%1], 16;" :: "r"(saddr), "l"(gptr));
}
__device__ __forceinline__ void cp_commit() { asm volatile("cp.async.commit_group;"); }

#define LDSM_X4(r0, r1, r2, r3, addr) \
    asm volatile("ldmatrix.sync.aligned.m8n8.x4.shared.b16 {%0,%1,%2,%3}, [%4];" \
        : "=r"(r0), "=r"(r1), "=r"(r2), "=r"(r3) : "r"(addr))

#define MMAF16(c, a, b0r, b1r) \
    asm volatile("mma.sync.aligned.m16n8k16.row.col.f32.f16.f16.f32 " \
        "{%0,%1,%2,%3}, {%4,%5,%6,%7}, {%8,%9}, {%0,%1,%2,%3};" \
        : "+f"((c)[0]), "+f"((c)[1]), "+f"((c)[2]), "+f"((c)[3]) \
        : "r"((a)[0]), "r"((a)[1]), "r"((a)[2]), "r"((a)[3]), "r"(b0r), "r"(b1r))

static __device__ __forceinline__ uint32_t sw128(uint32_t o) { return o ^ ((o >> 3) & 0x70); }

__device__ __forceinline__ float siluf(float x) { return x / (1.f + __expf(-x)); }

// ================= device scratch =================
__device__ float g_qkv [SEQ*NQKV];
__device__ float g_qp  [QBN*HQ*DH];
__device__ float g_kp  [QBN*HKV*DH];
__device__ float g_qg  [QBN*HQ*GHD];
__device__ float g_kg  [QBN*HKV*GHD];
__device__ unsigned char g_keep[HQ*QBN*QBN];
__device__ float g_h2  [SEQ*HID];

__device__ __half g_Wqkv2[NQKV*HID];
__device__ __half g_Wo2  [2048*2048];
__device__ __half g_Wgu2 [NGU*HID];      // interleaved: row 2j = gate_j, 2j+1 = up_j
__device__ __half g_Wd2  [2048*INTER];
__device__ __half g_ha2  [SEQ*HID];
__device__ __half g_oa2  [SEQ*HID];
__device__ __half g_h3a2 [SEQ*HID];
__device__ __half g_gt2  [SEQ*INTER];
__device__ __half g_qf16 [SEQ*HQ*DH];
__device__ __half g_kf16 [SEQ*HKV*DH];
__device__ __half g_vt16 [HKV*DH*SEQ];

// ===== side-stream resources (created pre-main in static init) =====
struct AuxRes {
    cudaStream_t s2;
    cudaEvent_t root, evQKV, evWo, evGU, evWd, evPool, evGate;
    AuxRes() {
        cudaStreamCreateWithFlags(&s2, cudaStreamNonBlocking);
        cudaEventCreateWithFlags(&root,   cudaEventDisableTiming);
        cudaEventCreateWithFlags(&evQKV,  cudaEventDisableTiming);
        cudaEventCreateWithFlags(&evWo,   cudaEventDisableTiming);
        cudaEventCreateWithFlags(&evGU,   cudaEventDisableTiming);
        cudaEventCreateWithFlags(&evWd,   cudaEventDisableTiming);
        cudaEventCreateWithFlags(&evPool, cudaEventDisableTiming);
        cudaEventCreateWithFlags(&evGate, cudaEventDisableTiming);
    }
};
static AuxRes g_aux;

// ===== fused QKV weight conversion: fp32 [K,N]x3 -> fp16 [3072, K] =====
__global__ void wconv3_kernel(const float* __restrict__ Wq, const float* __restrict__ Wk,
                              const float* __restrict__ Wv, __half* __restrict__ y) {
    __shared__ float tile[32][33];
    int n0 = blockIdx.x * 32, k0 = blockIdx.y * 32;
    const float* W; int sN, c0;
    if (n0 < 2048)      { W = Wq; sN = 2048; c0 = n0; }
    else if (n0 < 2560) { W = Wk; sN = 512;  c0 = n0 - 2048; }
    else                { W = Wv; sN = 512;  c0 = n0 - 2560; }
    for (int i = threadIdx.y; i < 32; i += 8)
        tile[i][threadIdx.x] = W[(size_t)(k0 + i) * sN + c0 + threadIdx.x];
    __syncthreads();
    for (int i = threadIdx.y; i < 32; i += 8) {
        int n = n0 + i, k = k0 + threadIdx.x;
        y[(size_t)n * HID + k] = __float2half_rn(tile[threadIdx.x][i]);
    }
}

// ===== weight conversion: fp32 [K,N] -> fp16 [N,K] =====
__global__ void wconv_kernel(const float* __restrict__ W, __half* __restrict__ y,
                             int K, int N) {
    __shared__ float tile[32][33];
    int n0 = blockIdx.x * 32, k0 = blockIdx.y * 32;
    for (int i = threadIdx.y; i < 32; i += 8)
        tile[i][threadIdx.x] = W[(size_t)(k0 + i) * N + n0 + threadIdx.x];
    __syncthreads();
    for (int i = threadIdx.y; i < 32; i += 8) {
        int n = n0 + i, k = k0 + threadIdx.x;
        y[(size_t)n * K + k] = __float2half_rn(tile[threadIdx.x][i]);
    }
}

// ===== interleaved gate/up weight conversion: rows 2j=gate_j, 2j+1=up_j =====
__global__ void wconvGU_kernel(const float* __restrict__ Wg, const float* __restrict__ Wu,
                               __half* __restrict__ y) {
    __shared__ float tg[32][33];
    __shared__ float tu[32][33];
    int j0 = blockIdx.x * 32, k0 = blockIdx.y * 32;
    for (int i = threadIdx.y; i < 32; i += 8) {
        tg[i][threadIdx.x] = Wg[(size_t)(k0 + i) * INTER + j0 + threadIdx.x];
        tu[i][threadIdx.x] = Wu[(size_t)(k0 + i) * INTER + j0 + threadIdx.x];
    }
    __syncthreads();
    for (int i = threadIdx.y; i < 32; i += 8) {
        int j = j0 + i, k = k0 + threadIdx.x;
        y[(size_t)(2 * j)     * HID + k] = __float2half_rn(tg[threadIdx.x][i]);
        y[(size_t)(2 * j + 1) * HID + k] = __float2half_rn(tu[threadIdx.x][i]);
    }
}

// ===== RMSNorm fused with fp16 conversion (vectorized) =====
__global__ void rmsconv_kernel(const float* __restrict__ x, const float* __restrict__ w,
                               __half* __restrict__ y) {
    const int row = blockIdx.x;
    const float4* xr4 = (const float4*)(x + (size_t)row * HID);
    const float4* w4  = (const float4*)w;
    const int t = threadIdx.x;

    float4 v0 = xr4[t], v1 = xr4[t + 256];
    float s = v0.x*v0.x + v0.y*v0.y + v0.z*v0.z + v0.w*v0.w
            + v1.x*v1.x + v1.y*v1.y + v1.z*v1.z + v1.w*v1.w;
    __shared__ float red[256];
    red[t] = s; __syncthreads();
    for (int st = 128; st > 0; st >>= 1) {
        if (t < st) red[t] += red[t + st];
        __syncthreads();
    }
    const float r = rsqrtf(red[0] / (float)HID + 1e-6f);

    float4 wa = w4[t], wb = w4[t + 256];
    __half2* yo = (__half2*)(y + (size_t)row * HID);
    yo[t * 2]             = __floats2half2_rn(wa.x * v0.x * r, wa.y * v0.y * r);
    yo[t * 2 + 1]         = __floats2half2_rn(wa.z * v0.z * r, wa.w * v0.w * r);
    yo[(t + 256) * 2]     = __floats2half2_rn(wb.x * v1.x * r, wb.y * v1.y * r);
    yo[(t + 256) * 2 + 1] = __floats2half2_rn(wb.z * v1.z * r, wb.w * v1.w * r);
}

// ====== fp16 HMMA GEMM, segs-limb A; optional fused SiLU(g)*u fp16 output ======
#define HG_SMEM 65536

__global__ void __launch_bounds__(256, 2) hgemm_kernel(
    const __half* __restrict__ A, const __half* __restrict__ B,
    const float* __restrict__ b1, const float* __restrict__ b2, const float* __restrict__ b3,
    int n1, int n2,
    const float* __restrict__ res,
    float* __restrict__ C, __half* __restrict__ Chalf,
    int N, int K, int segs)
{
    extern __shared__ char smraw[];
    const uint32_t smu = smem_u32(smraw);
    const int tid = threadIdx.x;
    const int lane = tid & 31, wid = tid >> 5;
    const int wm = wid >> 2, wn = wid & 3;
    const size_t ldaA = (size_t)segs * K;
    const size_t ldaB = (size_t)K;
    const int kpseg = K >> 6;
    const int nch = segs * kpseg;
    const size_t arow0 = (size_t)blockIdx.x * 128;
    const size_t brow0 = (size_t)blockIdx.y * 128;

    const uint32_t xm = (uint32_t)((lane & 7) << 4);
    uint32_t kbx[4];
#pragma unroll
    for (int ks = 0; ks < 4; ks++)
        kbx[ks] = ((uint32_t)(ks * 32 + ((lane >> 4) << 4))) ^ xm;
    uint32_t rowA[4], rowB[2];
#pragma unroll
    for (int mt = 0; mt < 4; mt++)
        rowA[mt] = (uint32_t)((wm << 6) + (lane & 15) + (mt << 4)) * 128u;
#pragma unroll
    for (int nt2 = 0; nt2 < 2; nt2++)
        rowB[nt2] = (uint32_t)((wn << 5) + (lane & 15) + (nt2 << 4)) * 128u;

    float acc[4][4][4];
#pragma unroll
    for (int i = 0; i < 4; i++)
#pragma unroll
        for (int j = 0; j < 4; j++)
#pragma unroll
            for (int t = 0; t < 4; t++) acc[i][j][t] = 0.f;

    auto issue = [&](int ch, int b) {
        int seg = ch / kpseg;
        int kk = (ch - seg * kpseg) << 6;
        const __half* Ab = A + (size_t)seg * K + kk;
        const __half* Bb = B + kk;
        uint32_t abase = smu + b * 32768;
        uint32_t bbase = abase + 16384;
#pragma unroll
        for (int i = 0; i < 4; i++) {
            int u = i * 256 + tid;
            int r = u >> 3, c = u & 7;
            uint32_t so = sw128((uint32_t)(r * 128 + c * 16));
            cp_async16(abase + so, Ab + (arow0 + r) * ldaA + c * 8);
            cp_async16(bbase + so, Bb + (brow0 + r) * ldaB + c * 8);
        }
        cp_commit();
    };

    issue(0, 0);

    for (int ch = 0; ch < nch; ch++) {
        const int b = ch & 1;
        if (ch + 1 < nch) {
            issue(ch + 1, b ^ 1);
            asm volatile("cp.async.wait_group 1;");
        } else {
            asm volatile("cp.async.wait_group 0;");
        }
        __syncthreads();

        const uint32_t abuf = smu + b * 32768;
        const uint32_t bbuf = abuf + 16384;

#pragma unroll
        for (int ks = 0; ks < 4; ks++) {
            uint32_t a[4][4];
#pragma unroll
            for (int mt = 0; mt < 4; mt++)
                LDSM_X4(a[mt][0], a[mt][1], a[mt][2], a[mt][3],
                        abuf + rowA[mt] + kbx[ks]);
            uint32_t bf[4][2];
#pragma unroll
            for (int nt2 = 0; nt2 < 2; nt2++) {
                uint32_t t0, t1, t2, t3;
                LDSM_X4(t0, t1, t2, t3, bbuf + rowB[nt2] + kbx[ks]);
                bf[nt2 * 2 + 0][0] = t0; bf[nt2 * 2 + 0][1] = t2;
                bf[nt2 * 2 + 1][0] = t1; bf[nt2 * 2 + 1][1] = t3;
            }
#pragma unroll
            for (int mt = 0; mt < 4; mt++)
#pragma unroll
                for (int nt = 0; nt < 4; nt++)
                    MMAF16(acc[mt][nt], a[mt], bf[nt][0], bf[nt][1]);
        }
        __syncthreads();
    }

    const int rbase = (int)arow0 + (wm << 6) + (lane >> 2);
    const int cbase = (int)brow0 + (wn << 5) + ((lane & 3) << 1);

    if (Chalf) {
        const int No = N >> 1;
#pragma unroll
        for (int nt = 0; nt < 4; nt++) {
            const int col = cbase + (nt << 3);
            const int oc = col >> 1;
#pragma unroll
            for (int mt = 0; mt < 4; mt++) {
                const int row = rbase + (mt << 4);
                float v0 = siluf(acc[mt][nt][0]) * acc[mt][nt][1];
                Chalf[(size_t)row * No + oc] = __float2half_rn(v0);
                float v1 = siluf(acc[mt][nt][2]) * acc[mt][nt][3];
                Chalf[(size_t)(row + 8) * No + oc] = __float2half_rn(v1);
            }
        }
        return;
    }

#pragma unroll
    for (int nt = 0; nt < 4; nt++) {
        const int col = cbase + (nt << 3);
        float bv0 = 0.f, bv1 = 0.f;
        if (b1) {
            if (col < n1)       { bv0 = b1[col];      bv1 = b1[col + 1]; }
            else if (col < n2)  { bv0 = b2[col - n1]; bv1 = b2[col - n1 + 1]; }
            else                { bv0 = b3[col - n2]; bv1 = b3[col - n2 + 1]; }
        }
#pragma unroll
        for (int mt = 0; mt < 4; mt++) {
            const int row = rbase + (mt << 4);
            size_t gi = (size_t)row * N + col;
            float v0 = acc[mt][nt][0] + bv0, v1 = acc[mt][nt][1] + bv1;
            if (res) { v0 += res[gi]; v1 += res[gi + 1]; }
            *(float2*)(C + gi) = make_float2(v0, v1);
            size_t gi2 = gi + (size_t)8 * N;
            float v2 = acc[mt][nt][2] + bv0, v3 = acc[mt][nt][3] + bv1;
            if (res) { v2 += res[gi2]; v3 += res[gi2 + 1]; }
            *(float2*)(C + gi2) = make_float2(v2, v3);
        }
    }
}

// ================= small fp32 SGEMM (gate path only) =================
__global__ void __launch_bounds__(256) sgemm_kernel(
    const float* __restrict__ A, const float* __restrict__ B,
    float* __restrict__ C, int M, int N, int K)
{
    __shared__ float As[8][128];
    __shared__ float Bs[8][128];
    const int tid = threadIdx.x;
    const int bx = blockIdx.x * 128;
    const int by = blockIdx.y * 128;
    const int tx = tid & 15;
    const int ty = tid >> 4;
    const int arow = tid >> 1;
    const int acol = (tid & 1) << 2;
    const int brow = tid >> 5;
    const int bcol = (tid & 31) << 2;

    const float* Ap = A + (size_t)(by + arow) * K + acol;
    const float* Bp = B + (size_t)brow * N + bx + bcol;

    float acc[8][8];
#pragma unroll
    for (int i = 0; i < 8; i++)
#pragma unroll
        for (int j = 0; j < 8; j++) acc[i][j] = 0.f;

    for (int k0 = 0; k0 < K; k0 += 8) {
        float4 av = *(const float4*)Ap;
        As[acol + 0][arow] = av.x;
        As[acol + 1][arow] = av.y;
        As[acol + 2][arow] = av.z;
        As[acol + 3][arow] = av.w;
        *(float4*)&Bs[brow][bcol] = *(const float4*)Bp;
        __syncthreads();
#pragma unroll
        for (int kk = 0; kk < 8; kk++) {
            float a[8], bb[8];
            *(float4*)&a[0] = *(const float4*)&As[kk][ty * 8];
            *(float4*)&a[4] = *(const float4*)&As[kk][ty * 8 + 4];
            *(float4*)&bb[0] = *(const float4*)&Bs[kk][tx * 8];
            *(float4*)&bb[4] = *(const float4*)&Bs[kk][tx * 8 + 4];
#pragma unroll
            for (int i = 0; i < 8; i++)
#pragma unroll
                for (int j = 0; j < 8; j++)
                    acc[i][j] += a[i] * bb[j];
        }
        __syncthreads();
        Ap += 8;
        Bp += (size_t)8 * N;
    }

    const int row0 = by + ty * 8;
    const int col0 = bx + tx * 8;
#pragma unroll
    for (int i = 0; i < 8; i++)
#pragma unroll
        for (int j = 0; j < 8; j++)
            C[(size_t)(row0 + i) * N + col0 + j] = acc[i][j];
}

// ================= pooling / gate =================
__global__ void pool_kernel(const float* __restrict__ x, int stride,
                            float* __restrict__ out, int H) {
    int qb = blockIdx.x, h = blockIdx.y, d = threadIdx.x;
    float s = 0.f;
    for (int i = 0; i < BSZ; i++)
        s += x[(size_t)(qb * BSZ + i) * stride + h * DH + d];
    out[((size_t)qb * H + h) * DH + d] = s * (1.f / (float)BSZ);
}

__global__ void gate_kernel(const float* __restrict__ qg, const float* __restrict__ kg,
                            unsigned char* __restrict__ keep) {
    int h = blockIdx.x, qb = blockIdx.y, kb = threadIdx.x;
    const float* qv = qg + ((size_t)qb * HQ + h) * GHD;
    const float* kv = kg + ((size_t)kb * HKV + (h >> 2)) * GHD;
    float s = 0.f;
    for (int d = 0; d < GHD; d++) s += qv[d] * kv[d];
    s *= SCALE_INV_SQRT_128;
    if (kb > qb) s = -1e30f;
    float m = s;
    for (int off = 16; off > 0; off >>= 1)
        m = fmaxf(m, __shfl_xor_sync(0xffffffffu, m, off));
    float e = expf(s - m);
    float sum = e;
    for (int off = 16; off > 0; off >>= 1)
        sum += __shfl_xor_sync(0xffffffffu, sum, off);
    float gate = e / sum;
    bool kp = (kb <= qb) && ((gate >= 0.004f) || (kb == qb));
    keep[((size_t)h * QBN + qb) * QBN + kb] = kp ? 1 : 0;
}

// ===== RoPE + fp16 conversion (vectorized: float2 pairs, half2 stores) =====
__global__ void ropeconv_kernel(const float* __restrict__ qkv,
                                const float* __restrict__ cs, const float* __restrict__ sn,
                                __half* __restrict__ qf, __half* __restrict__ kf) {
    const int t = blockIdx.x;
    const float* row = qkv + (size_t)t * NQKV;
    const float2* c2 = (const float2*)(cs + (size_t)t * DH);
    const float2* s2 = (const float2*)(sn + (size_t)t * DH);
    __half2* qo = (__half2*)(qf + (size_t)t * (HQ*DH));
    __half2* ko = (__half2*)(kf + (size_t)t * (HKV*DH));

    for (int i = threadIdx.x; i < HQ * 32; i += 256) {
        int hh = i >> 5, d2 = i & 31;           // d = d2*2
        const float2* rp = (const float2*)(row + hh * DH);
        float2 x1 = rp[d2], x2 = rp[d2 + 32];
        float2 c1 = c2[d2], s1 = s2[d2];
        float2 cb = c2[d2 + 32], sb = s2[d2 + 32];
        qo[hh * 64 + d2] = __floats2half2_rn(
            (x1.x * c1.x - x2.x * s1.x) * SCALE_INV_SQRT_128,
            (x1.y * c1.y - x2.y * s1.y) * SCALE_INV_SQRT_128);
        qo[hh * 64 + d2 + 32] = __floats2half2_rn(
            (x2.x * cb.x + x1.x * sb.x) * SCALE_INV_SQRT_128,
            (x2.y * cb.y + x1.y * sb.y) * SCALE_INV_SQRT_128);
    }
    for (int i = threadIdx.x; i < HKV * 32; i += 256) {
        int hh = i >> 5, d2 = i & 31;
        const float2* rp = (const float2*)(row + 2048 + hh * DH);
        float2 x1 = rp[d2], x2 = rp[d2 + 32];
        float2 c1 = c2[d2], s1 = s2[d2];
        float2 cb = c2[d2 + 32], sb = s2[d2 + 32];
        ko[hh * 64 + d2] = __floats2half2_rn(
            x1.x * c1.x - x2.x * s1.x,
            x1.y * c1.y - x2.y * s1.y);
        ko[hh * 64 + d2 + 32] = __floats2half2_rn(
            x2.x * cb.x + x1.x * sb.x,
            x2.y * cb.y + x1.y * sb.y);
    }
}

// ===== V transpose + fp16 =====
__global__ void vconvt_kernel(const float* __restrict__ qkv, __half* __restrict__ vt) {
    __shared__ float tile[32][33];
    int t0 = blockIdx.x * 32, d0 = blockIdx.y * 32, hk = blockIdx.z;
    for (int i = threadIdx.y; i < 32; i += 8)
        tile[i][threadIdx.x] = qkv[(size_t)(t0 + i) * NQKV + 2560 + hk * DH + d0 + threadIdx.x];
    __syncthreads();
    for (int i = threadIdx.y; i < 32; i += 8) {
        int d = d0 + i, t = t0 + threadIdx.x;
        vt[((size_t)hk * DH + d) * SEQ + t] = __float2half_rn(tile[threadIdx.x][i]);
    }
}

// ================= fp16 tensor-core block-sparse flash attention =================
#define QKP 136
#define VTP 72
#define PSP 72
#define FS_OFF 62464
#define ATTN_SMEM (FS_OFF + 448*4)

__global__ void __launch_bounds__(256, 2) attn_kernel(
    const __half* __restrict__ qf, const __half* __restrict__ kf,
    const __half* __restrict__ vt,
    const unsigned char* __restrict__ keep, __half* __restrict__ oa2)
{
    extern __shared__ char smc[];
    __half* QS = (__half*)smc;
    __half* KS = QS + 64 * QKP;
    __half* VT = KS + 64 * QKP;
    __half* PS = VT + 128 * VTP;
    float* fs = (float*)(smc + FS_OFF);
    float* ARM = fs; float* ARL = fs + 128;
    float* ROWM = fs + 256; float* ROWL = fs + 320; float* ALF = fs + 384;

    const int qb = QBN - 1 - blockIdx.x;
    const int h = blockIdx.y;
    const int hk = h >> 2;
    const int tid = threadIdx.x;
    const int lane = tid & 31, wid = tid >> 5;
    const int rw = wid & 3, cw = wid >> 2;
    const int g = lane >> 2, qd = lane & 3;
    const int r0 = rw * 16 + g;
    const int r1 = r0 + 8;
    const int q2 = qd * 2;

    for (int i = tid; i < 64 * 16; i += 256) {
        int r = i >> 4, c = i & 15;
        *(uint4*)&QS[r * QKP + c * 8] =
            *(const uint4*)&qf[(size_t)(qb * 64 + r) * (HQ*DH) + h * DH + c * 8];
    }
    if (tid < 64) { ROWM[tid] = -1e30f; ROWL[tid] = 0.f; }

    float oacc[8][4];
#pragma unroll
    for (int i = 0; i < 8; i++)
#pragma unroll
        for (int j = 0; j < 4; j++) oacc[i][j] = 0.f;

    const unsigned char* krow = keep + ((size_t)h * QBN + qb) * QBN;

    for (int kb = 0; kb <= qb; kb++) {
        if (!krow[kb]) continue;
        __syncthreads();

        for (int i = tid; i < 64 * 16; i += 256) {
            int r = i >> 4, c = i & 15;
            *(uint4*)&KS[r * QKP + c * 8] =
                *(const uint4*)&kf[(size_t)(kb * 64 + r) * (HKV*DH) + hk * DH + c * 8];
        }
        for (int i = tid; i < 128 * 8; i += 256) {
            int d = i >> 3, c = i & 7;
            *(uint4*)&VT[d * VTP + c * 8] =
                *(const uint4*)&vt[((size_t)hk * DH + d) * SEQ + kb * 64 + c * 8];
        }
        __syncthreads();

        float sacc[4][4];
#pragma unroll
        for (int i = 0; i < 4; i++)
#pragma unroll
            for (int j = 0; j < 4; j++) sacc[i][j] = 0.f;

#pragma unroll
        for (int kc = 0; kc < 8; kc++) {
            const int k0 = kc * 16;
            uint32_t a[4];
            a[0] = *(const uint32_t*)&QS[r0 * QKP + k0 + q2];
            a[1] = *(const uint32_t*)&QS[r1 * QKP + k0 + q2];
            a[2] = *(const uint32_t*)&QS[r0 * QKP + k0 + q2 + 8];
            a[3] = *(const uint32_t*)&QS[r1 * QKP + k0 + q2 + 8];
#pragma unroll
            for (int nt = 0; nt < 4; nt++) {
                const int n = cw * 32 + nt * 8 + g;
                uint32_t b0 = *(const uint32_t*)&KS[n * QKP + k0 + q2];
                uint32_t b1 = *(const uint32_t*)&KS[n * QKP + k0 + q2 + 8];
                MMAF16(sacc[nt], a, b0, b1);
            }
        }

        if (kb == qb) {
#pragma unroll
            for (int nt = 0; nt < 4; nt++) {
                const int c0 = cw * 32 + nt * 8 + q2;
                if (c0 > r0)     sacc[nt][0] = -1e30f;
                if (c0 + 1 > r0) sacc[nt][1] = -1e30f;
                if (c0 > r1)     sacc[nt][2] = -1e30f;
                if (c0 + 1 > r1) sacc[nt][3] = -1e30f;
            }
        }

        float m0 = -1e30f, m1 = -1e30f;
#pragma unroll
        for (int nt = 0; nt < 4; nt++) {
            m0 = fmaxf(m0, fmaxf(sacc[nt][0], sacc[nt][1]));
            m1 = fmaxf(m1, fmaxf(sacc[nt][2], sacc[nt][3]));
        }
        m0 = fmaxf(m0, __shfl_xor_sync(0xffffffffu, m0, 1));
        m0 = fmaxf(m0, __shfl_xor_sync(0xffffffffu, m0, 2));
        m1 = fmaxf(m1, __shfl_xor_sync(0xffffffffu, m1, 1));
        m1 = fmaxf(m1, __shfl_xor_sync(0xffffffffu, m1, 2));
        if (qd == 0) {
            ARM[cw * 64 + r0] = m0;
            ARM[cw * 64 + r1] = m1;
        }
        __syncthreads();

        if (tid < 64) {
            float newm = fmaxf(ROWM[tid], fmaxf(ARM[tid], ARM[64 + tid]));
            ALF[tid] = __expf(ROWM[tid] - newm);
            ROWM[tid] = newm;
        }
        __syncthreads();

        const float nm0 = ROWM[r0];
        const float nm1 = ROWM[r1];
        float l0 = 0.f, l1 = 0.f;
#pragma unroll
        for (int nt = 0; nt < 4; nt++) {
            const int c0 = cw * 32 + nt * 8 + q2;
            float p0 = __expf(sacc[nt][0] - nm0);
            float p1 = __expf(sacc[nt][1] - nm0);
            float p2 = __expf(sacc[nt][2] - nm1);
            float p3 = __expf(sacc[nt][3] - nm1);
            l0 += p0 + p1; l1 += p2 + p3;
            *(__half2*)&PS[r0 * PSP + c0] = __floats2half2_rn(p0, p1);
            *(__half2*)&PS[r1 * PSP + c0] = __floats2half2_rn(p2, p3);
        }
        l0 += __shfl_xor_sync(0xffffffffu, l0, 1);
        l0 += __shfl_xor_sync(0xffffffffu, l0, 2);
        l1 += __shfl_xor_sync(0xffffffffu, l1, 1);
        l1 += __shfl_xor_sync(0xffffffffu, l1, 2);
        if (qd == 0) {
            ARL[cw * 64 + r0] = l0;
            ARL[cw * 64 + r1] = l1;
        }
        const float al0 = ALF[r0];
        const float al1 = ALF[r1];
#pragma unroll
        for (int nt = 0; nt < 8; nt++) {
            oacc[nt][0] *= al0; oacc[nt][1] *= al0;
            oacc[nt][2] *= al1; oacc[nt][3] *= al1;
        }
        __syncthreads();

        if (tid < 64)
            ROWL[tid] = ROWL[tid] * ALF[tid] + ARL[tid] + ARL[64 + tid];

#pragma unroll
        for (int kc = 0; kc < 4; kc++) {
            const int k0 = kc * 16;
            uint32_t a[4];
            a[0] = *(const uint32_t*)&PS[r0 * PSP + k0 + q2];
            a[1] = *(const uint32_t*)&PS[r1 * PSP + k0 + q2];
            a[2] = *(const uint32_t*)&PS[r0 * PSP + k0 + q2 + 8];
            a[3] = *(const uint32_t*)&PS[r1 * PSP + k0 + q2 + 8];
#pragma unroll
            for (int nt = 0; nt < 8; nt++) {
                const int n = cw * 64 + nt * 8 + g;
                uint32_t b0 = *(const uint32_t*)&VT[n * VTP + k0 + q2];
                uint32_t b1 = *(const uint32_t*)&VT[n * VTP + k0 + q2 + 8];
                MMAF16(oacc[nt], a, b0, b1);
            }
        }
    }

    __syncthreads();
    const float inv0 = 1.f / ROWL[r0];
    const float inv1 = 1.f / ROWL[r1];
    const size_t grow0 = (size_t)(qb * 64 + r0);
    const size_t grow1 = (size_t)(qb * 64 + r1);
#pragma unroll
    for (int nt = 0; nt < 8; nt++) {
        const int col = h * DH + cw * 64 + nt * 8 + q2;
        *(__half2*)(oa2 + grow0 * HID + col) =
            __floats2half2_rn(oacc[nt][0] * inv0, oacc[nt][1] * inv0);
        *(__half2*)(oa2 + grow1 * HID + col) =
            __floats2half2_rn(oacc[nt][2] * inv1, oacc[nt][3] * inv1);
    }
}

// ================= launch =================
extern "C" void kernel_launch(void* const* d_in, const int* in_sizes, int n_in,
                              void* d_out, int out_size) {
    const float* hidden = (const float*)d_in[0];
    const float* cosp   = (const float*)d_in[1];
    const float* sinp   = (const float*)d_in[2];
    const float* ln1    = (const float*)d_in[3];
    const float* ln2    = (const float*)d_in[4];
    const float* Wq     = (const float*)d_in[5];
    const float* bq     = (const float*)d_in[6];
    const float* Wk     = (const float*)d_in[7];
    const float* bk     = (const float*)d_in[8];
    const float* Wv     = (const float*)d_in[9];
    const float* bv     = (const float*)d_in[10];
    const float* Wo     = (const float*)d_in[11];
    const float* gWq    = (const float*)d_in[12];
    const float* gWk    = (const float*)d_in[13];
    const float* Wgate  = (const float*)d_in[14];
    const float* Wup    = (const float*)d_in[15];
    const float* Wdown  = (const float*)d_in[16];
    float* out = (float*)d_out;

    float *qkv, *qp, *kp, *qg, *kg, *h2;
    unsigned char* keep;
    __half *Wqkv2, *Wo2, *Wgu2, *Wd2, *ha2, *oa2, *h3a2, *gt2, *qf16, *kf16, *vt16;
    cudaGetSymbolAddress((void**)&qkv,  g_qkv);
    cudaGetSymbolAddress((void**)&qp,   g_qp);
    cudaGetSymbolAddress((void**)&kp,   g_kp);
    cudaGetSymbolAddress((void**)&qg,   g_qg);
    cudaGetSymbolAddress((void**)&kg,   g_kg);
    cudaGetSymbolAddress((void**)&keep, g_keep);
    cudaGetSymbolAddress((void**)&h2,   g_h2);
    cudaGetSymbolAddress((void**)&Wqkv2, g_Wqkv2);
    cudaGetSymbolAddress((void**)&Wo2,  g_Wo2);
    cudaGetSymbolAddress((void**)&Wgu2, g_Wgu2);
    cudaGetSymbolAddress((void**)&Wd2,  g_Wd2);
    cudaGetSymbolAddress((void**)&ha2,  g_ha2);
    cudaGetSymbolAddress((void**)&oa2,  g_oa2);
    cudaGetSymbolAddress((void**)&h3a2, g_h3a2);
    cudaGetSymbolAddress((void**)&gt2,  g_gt2);
    cudaGetSymbolAddress((void**)&qf16, g_qf16);
    cudaGetSymbolAddress((void**)&kf16, g_kf16);
    cudaGetSymbolAddress((void**)&vt16, g_vt16);

    cudaFuncSetAttribute(hgemm_kernel, cudaFuncAttributeMaxDynamicSharedMemorySize, HG_SMEM);
    cudaFuncSetAttribute(attn_kernel, cudaFuncAttributeMaxDynamicSharedMemorySize, ATTN_SMEM);

    dim3 w8(32, 8);
    cudaStream_t s2 = g_aux.s2;

    // ---- fork side stream: weight conversions + gate path off critical path ----
    cudaEventRecord(g_aux.root, 0);
    cudaStreamWaitEvent(s2, g_aux.root, 0);
    wconv3_kernel<<<dim3(NQKV/32, HID/32), w8, 0, s2>>>(Wq, Wk, Wv, Wqkv2);
    cudaEventRecord(g_aux.evQKV, s2);
    wconv_kernel<<<dim3(HID/32, HID/32), w8, 0, s2>>>(Wo, Wo2, HID, HID);
    cudaEventRecord(g_aux.evWo, s2);
    wconvGU_kernel<<<dim3(INTER/32, HID/32), w8, 0, s2>>>(Wgate, Wup, Wgu2);
    cudaEventRecord(g_aux.evGU, s2);
    wconv_kernel<<<dim3(HID/32, INTER/32), w8, 0, s2>>>(Wdown, Wd2, INTER, HID);
    cudaEventRecord(g_aux.evWd, s2);

    // ---- main chain ----
    rmsconv_kernel<<<SEQ, 256>>>(hidden, ln1, ha2);
    cudaStreamWaitEvent(0, g_aux.evQKV, 0);
    hgemm_kernel<<<dim3(SEQ/128, NQKV/128), 256, HG_SMEM>>>(
        ha2, Wqkv2, bq, bk, bv, 2048, 2560, nullptr, qkv, nullptr, NQKV, HID, 1);

    // gate path on s2 overlapping rope/V conversions (qkv is never mutated)
    pool_kernel<<<dim3(QBN, HQ), DH>>>(qkv, NQKV, qp, HQ);
    pool_kernel<<<dim3(QBN, HKV), DH>>>(qkv + 2048, NQKV, kp, HKV);
    cudaEventRecord(g_aux.evPool, 0);
    cudaStreamWaitEvent(s2, g_aux.evPool, 0);
    sgemm_kernel<<<dim3(GHD/128, (QBN*HQ)/128), 256, 0, s2>>>(qp, gWq, qg, QBN*HQ, GHD, DH);
    sgemm_kernel<<<dim3(GHD/128, (QBN*HKV)/128), 256, 0, s2>>>(kp, gWk, kg, QBN*HKV, GHD, DH);
    gate_kernel<<<dim3(HQ, QBN), 32, 0, s2>>>(qg, kg, keep);
    cudaEventRecord(g_aux.evGate, s2);

    ropeconv_kernel<<<SEQ, 256>>>(qkv, cosp, sinp, qf16, kf16);
    vconvt_kernel<<<dim3(SEQ/32, DH/32, HKV), w8>>>(qkv, vt16);

    cudaStreamWaitEvent(0, g_aux.evGate, 0);
    attn_kernel<<<dim3(QBN, HQ), 256, ATTN_SMEM>>>(qf16, kf16, vt16, keep, oa2);

    cudaStreamWaitEvent(0, g_aux.evWo, 0);
    hgemm_kernel<<<dim3(SEQ/128, HID/128), 256, HG_SMEM>>>(
        oa2, Wo2, nullptr, nullptr, nullptr, HID, HID, hidden, h2, nullptr, HID, HQ*DH, 1);

    rmsconv_kernel<<<SEQ, 256>>>(h2, ln2, h3a2);

    // gate|up GEMM with fused SiLU epilogue -> gt2 fp16
    cudaStreamWaitEvent(0, g_aux.evGU, 0);
    hgemm_kernel<<<dim3(SEQ/128, NGU/128), 256, HG_SMEM>>>(
        h3a2, Wgu2, nullptr, nullptr, nullptr, NGU, NGU, nullptr, nullptr, gt2, NGU, HID, 1);

    cudaStreamWaitEvent(0, g_aux.evWd, 0);
    hgemm_kernel<<<dim3(SEQ/128, HID/128), 256, HG_SMEM>>>(
        gt2, Wd2, nullptr, nullptr, nullptr, HID, HID, h2, out, nullptr, HID, INTER, 1);
}